// round 17
// baseline (speedup 1.0000x reference)
#include <cuda_runtime.h>
#include <cstdint>

#define MM 4096
#define NN 4096
#define KK 4096
#define BM 128
#define BN 128
#define BK 32
#define NKT (KK / BK)             // 128 k-iterations
#define AS_BYTES 8192             // 128 rows x 64B fp16 (swizzled)
#define BS_BYTES 8192             // 2 k16-blocks x 128 cols x 32B
#define SMEM_BYTES (2 * AS_BYTES + 2 * BS_BYTES)  // 32768

static __device__ __forceinline__ uint32_t s2u(const void* p) {
    uint32_t a;
    asm("{ .reg .u64 t; cvta.to.shared.u64 t, %1; cvt.u32.u64 %0, t; }" : "=r"(a) : "l"(p));
    return a;
}

// pack two f32 -> f16x2 {lo, hi}, round-nearest
static __device__ __forceinline__ uint32_t pack_h2(float lo, float hi) {
    uint32_t r;
    asm("cvt.rn.f16x2.f32 %0, %1, %2;" : "=r"(r) : "f"(hi), "f"(lo));
    return r;
}

// nibble kk of packed word -> float bits of exact (16 + nib): shift + lop3
template <int KKI>
static __device__ __forceinline__ float nib16(uint32_t p) {
    uint32_t t = (KKI < 5) ? (p << (19 - 4 * KKI)) : (p >> (4 * KKI - 19));
    return __uint_as_float((t & 0x00780000u) | 0x41800000u);
}

static __device__ __forceinline__ void sts128(uint32_t a, uint32_t r0, uint32_t r1,
                                              uint32_t r2, uint32_t r3) {
    asm volatile("st.shared.v4.b32 [%0], {%1,%2,%3,%4};"
                 :: "r"(a), "r"(r0), "r"(r1), "r"(r2), "r"(r3) : "memory");
}

static __device__ __forceinline__ void lds64(uint32_t a, uint32_t& r0, uint32_t& r1) {
    asm volatile("ld.shared.v2.b32 {%0,%1}, [%2];" : "=r"(r0), "=r"(r1) : "r"(a));
}

static __device__ __forceinline__ void ldmx4(uint32_t a, uint32_t* r) {
    asm volatile("ldmatrix.sync.aligned.m8n8.x4.shared.b16 {%0,%1,%2,%3}, [%4];"
                 : "=r"(r[0]), "=r"(r[1]), "=r"(r[2]), "=r"(r[3]) : "r"(a));
}

__global__ void __launch_bounds__(128, 2)
gemm_w4(const float* __restrict__ x, const int* __restrict__ wq,
        const float* __restrict__ scales, const float* __restrict__ zeros,
        const float* __restrict__ bias, float* __restrict__ out)
{
    extern __shared__ char smem[];
    const uint32_t sb = s2u(smem);
    const uint32_t xs = sb;                     // 2 x AS_BYTES
    const uint32_t ws = sb + 2 * AS_BYTES;      // 2 x BS_BYTES

    const int tid = threadIdx.x;
    const int lane = tid & 31;
    const int warp = tid >> 5;
    const int wm = warp >> 1;  // 0..1 (M, 64 rows)
    const int wn = warp & 1;   // 0..1 (N, 64 cols)
    const int bm0 = blockIdx.y * BM;
    const int bn0 = blockIdx.x * BN;

    // ---------------- producer mapping ----------------
    // A: thread owns full row tid (32 fp32 -> 16 f16x2 -> 4 STS.128)
    const int rowA = tid;
    const uint32_t asw = (uint32_t)((rowA >> 1) & 3);
    const uint32_t a_row_off = (uint32_t)rowA * 64;
    const float* xrow = x + (size_t)(bm0 + rowA) * KK;

    // B: thread owns column tid, both k16 blocks (4 packed words)
    const int nB = tid;
    const int gB = nB >> 2, qB = nB & 3, pgB = gB & 1;
    const uint32_t b_sts0 = (uint32_t)(gB * 128 + ((qB + 4 * pgB) << 4));
    const uint32_t b_sts1 = (uint32_t)(gB * 128 + ((qB + 4 * (1 ^ pgB)) << 4));
    const int gn = bn0 + nB;

    // ---------------- consumer mapping ----------------
    const int ahalf = lane >> 4;
    const int rsw = ((lane & 15) >> 1) & 3;
    const uint32_t a_ld_base = (uint32_t)(wm * 4096 + (lane & 15) * 64);
    const int cB = lane & 3;
    const uint32_t Lb = (uint32_t)((lane >> 4) * 128 + (((lane >> 2) & 3) << 4)
                                 + (((cB >> 1) ^ (lane >> 4)) << 6) + ((cB & 1) << 3));
    const uint32_t b_ld_base = (uint32_t)(wn * 2048) + Lb;

    float acc[4][8][4];
#pragma unroll
    for (int mf = 0; mf < 4; mf++)
#pragma unroll
        for (int nf = 0; nf < 8; nf++)
#pragma unroll
            for (int r = 0; r < 4; r++) acc[mf][nf][r] = 0.0f;

    uint32_t ap[16];   // A row packed f16x2 (k0..k31)
    int wr[4];         // 4 packed B words
    float sv, c2;

    auto fetch = [&](int kt) {
#pragma unroll
        for (int f = 0; f < 8; f++) {
            const float4 v = *(const float4*)(xrow + (size_t)kt * BK + f * 4);
            ap[2 * f + 0] = pack_h2(v.x, v.y);
            ap[2 * f + 1] = pack_h2(v.z, v.w);
        }
#pragma unroll
        for (int i = 0; i < 4; i++)
            wr[i] = wq[(size_t)(kt * 4 + i) * NN + gn];
        const int g = kt >> 2;
        const float s = scales[(size_t)g * NN + gn];
        const float z = zeros[(size_t)g * NN + gn];
        sv = s;
        c2 = -(z + 16.0f) * s;
    };

    auto stage = [&](int buf) {
        // A: 4 chunks of 16B, XOR-swizzled
        const uint32_t xb = xs + (uint32_t)buf * AS_BYTES + a_row_off;
#pragma unroll
        for (uint32_t c = 0; c < 4; c++)
            sts128(xb + ((c ^ asw) << 4), ap[4 * c + 0], ap[4 * c + 1],
                   ap[4 * c + 2], ap[4 * c + 3]);
        // B: dequant both k16 blocks
        const uint32_t wb = ws + (uint32_t)buf * BS_BYTES;
#pragma unroll
        for (int blk = 0; blk < 2; blk++) {
            const uint32_t pe = (uint32_t)wr[2 * blk + 0];
            const uint32_t po = (uint32_t)wr[2 * blk + 1];
            uint32_t e0 = pack_h2(fmaf(nib16<0>(pe), sv, c2), fmaf(nib16<1>(pe), sv, c2));
            uint32_t e1 = pack_h2(fmaf(nib16<2>(pe), sv, c2), fmaf(nib16<3>(pe), sv, c2));
            uint32_t e2 = pack_h2(fmaf(nib16<4>(pe), sv, c2), fmaf(nib16<5>(pe), sv, c2));
            uint32_t e3 = pack_h2(fmaf(nib16<6>(pe), sv, c2), fmaf(nib16<7>(pe), sv, c2));
            uint32_t o0 = pack_h2(fmaf(nib16<0>(po), sv, c2), fmaf(nib16<1>(po), sv, c2));
            uint32_t o1 = pack_h2(fmaf(nib16<2>(po), sv, c2), fmaf(nib16<3>(po), sv, c2));
            uint32_t o2 = pack_h2(fmaf(nib16<4>(po), sv, c2), fmaf(nib16<5>(po), sv, c2));
            uint32_t o3 = pack_h2(fmaf(nib16<6>(po), sv, c2), fmaf(nib16<7>(po), sv, c2));
            const uint32_t bbase = wb + (uint32_t)(blk * 4096);
            sts128(bbase + b_sts0, e0, o0, e1, o1);
            sts128(bbase + b_sts1, e2, o2, e3, o3);
        }
    };

    // ---- prologue: fetch + stage tile 0 into buffer 0 ----
    fetch(0);
    stage(0);
    __syncthreads();

#pragma unroll 1
    for (int kt = 0; kt < NKT; ++kt) {
        const int cur = kt & 1;

        // prefetch tile kt+1 into registers (consumed by stage() below)
        if (kt + 1 < NKT) fetch(kt + 1);

        const uint32_t xb = xs + (uint32_t)cur * AS_BYTES;
        const uint32_t wbuf = ws + (uint32_t)cur * BS_BYTES;

#pragma unroll
        for (int ks = 0; ks < 2; ks++) {
            uint32_t a[4][4];
#pragma unroll
            for (int mf = 0; mf < 4; mf++)
                ldmx4(xb + a_ld_base + (uint32_t)(mf * 1024)
                         + (uint32_t)((((ks << 1) | ahalf) ^ rsw) << 4), a[mf]);
#pragma unroll
            for (int nf = 0; nf < 8; nf++) {
                uint32_t b0, b1;
                lds64(wbuf + (uint32_t)(ks * 4096) + b_ld_base + (uint32_t)(nf * 256), b0, b1);
#pragma unroll
                for (int mf = 0; mf < 4; mf++)
                    asm("mma.sync.aligned.m16n8k16.row.col.f32.f16.f16.f32 "
                        "{%0,%1,%2,%3}, {%4,%5,%6,%7}, {%8,%9}, {%0,%1,%2,%3};"
                        : "+f"(acc[mf][nf][0]), "+f"(acc[mf][nf][1]),
                          "+f"(acc[mf][nf][2]), "+f"(acc[mf][nf][3])
                        : "r"(a[mf][0]), "r"(a[mf][1]), "r"(a[mf][2]), "r"(a[mf][3]),
                          "r"(b0), "r"(b1));
            }
        }

        // stage tile kt+1 into the other buffer; single barrier per tile
        if (kt + 1 < NKT) {
            stage(cur ^ 1);
            __syncthreads();
        }
    }

    // ---- epilogue: add bias, write out ----
#pragma unroll
    for (int mf = 0; mf < 4; mf++) {
        const int rm = bm0 + wm * 64 + mf * 16 + (lane >> 2);
#pragma unroll
        for (int nf = 0; nf < 8; nf++) {
            const int cn = bn0 + wn * 64 + nf * 8 + 2 * (lane & 3);
            const float2 bv = *(const float2*)&bias[cn];
            float2 o0 = make_float2(acc[mf][nf][0] + bv.x, acc[mf][nf][1] + bv.y);
            float2 o1 = make_float2(acc[mf][nf][2] + bv.x, acc[mf][nf][3] + bv.y);
            *(float2*)&out[(size_t)rm * NN + cn] = o0;
            *(float2*)&out[(size_t)(rm + 8) * NN + cn] = o1;
        }
    }
}

extern "C" void kernel_launch(void* const* d_in, const int* in_sizes, int n_in,
                              void* d_out, int out_size) {
    const float* x      = (const float*)d_in[0];
    const int*   wq     = (const int*)d_in[1];
    const float* scales = (const float*)d_in[2];
    const float* zeros  = (const float*)d_in[3];
    const float* bias   = (const float*)d_in[4];
    float* out = (float*)d_out;

    cudaFuncSetAttribute(gemm_w4, cudaFuncAttributeMaxDynamicSharedMemorySize, SMEM_BYTES);
    dim3 grid(NN / BN, MM / BM);  // 32 x 32 = 1024 CTAs
    gemm_w4<<<grid, 128, SMEM_BYTES>>>(x, wq, scales, zeros, bias, out);
}